// round 12
// baseline (speedup 1.0000x reference)
#include <cuda_runtime.h>
#include <math.h>

#define MAX_N    131072
#define NGRAPH   256
#define MAXSEG   1024
#define RSPLIT   4
#define NBINS    2048
#define CHUNKB   8       // bins per thread (2048/256)

// Scratch (static __device__ arrays — no allocation allowed)
__device__ float d_p[MAX_N];        // x[i] . w_rel
__device__ float d_r[MAX_N];        // x[i] . w_root
__device__ float d_s[MAX_N];        // segment-summed p over edges
__device__ float d_score[MAX_N];    // fallback scratch only
__device__ float d_w[MAX_N];        // fallback scratch only

__device__ __forceinline__ unsigned score_key(float s) {
    unsigned u = __float_as_uint(s);
    return (u & 0x80000000u) ? ~u : (u | 0x80000000u);   // monotone
}
__device__ __forceinline__ float key_score(unsigned k) {
    return (k & 0x80000000u) ? __uint_as_float(k & 0x7fffffffu)
                             : __uint_as_float(~k);
}
__device__ __forceinline__ int lower_bound_i(const int* a, int n, int v) {
    int lo = 0, hi = n;
    while (lo < hi) {
        int mid = (lo + hi) >> 1;
        if (a[mid] < v) lo = mid + 1; else hi = mid;
    }
    return lo;
}
__device__ __forceinline__ float dot4(float4 a, float4 b) {
    return a.x * b.x + a.y * b.y + a.z * b.z + a.w * b.w;
}

// ---------------------------------------------------------------------------
// K0: per-node dots (8 threads/node, 2x float4) ; zero s ; zero out.
// ---------------------------------------------------------------------------
__global__ void k_node_dots(const float* __restrict__ x,
                            const float* __restrict__ w_rel,
                            const float* __restrict__ w_root,
                            float* __restrict__ out,
                            int N) {
    int gid = blockIdx.x * blockDim.x + threadIdx.x;
    if (gid < NGRAPH * 64) out[gid] = 0.0f;
    int node = gid >> 3;
    if (node >= N) return;
    int sub = gid & 7;
    const float4* xr = (const float4*)(x + (size_t)node * 64);
    float4 v0 = xr[sub];
    float4 v1 = xr[sub + 8];
    const float4* wrv = (const float4*)w_rel;
    const float4* wtv = (const float4*)w_root;
    float a = dot4(v0, wrv[sub]) + dot4(v1, wrv[sub + 8]);
    float b = dot4(v0, wtv[sub]) + dot4(v1, wtv[sub + 8]);
#pragma unroll
    for (int o = 4; o; o >>= 1) {
        a += __shfl_xor_sync(0xffffffffu, a, o);
        b += __shfl_xor_sync(0xffffffffu, b, o);
    }
    if (sub == 0) {
        d_p[node] = a;
        d_r[node] = b;
        d_s[node] = 0.0f;
    }
}

// ---------------------------------------------------------------------------
// K1: edge scatter  s[dst] += p[src].  8 edges/thread; tail folded in.
// ---------------------------------------------------------------------------
__global__ void k_edge_scatter(const int* __restrict__ ei, int E) {
    int t = blockIdx.x * blockDim.x + threadIdx.x;
    int E8 = E >> 3;
    if (t < E8) {
        const int4* sv = (const int4*)ei;
        const int4* dv = (const int4*)(ei + E);
        int4 sa = sv[2 * t], sb = sv[2 * t + 1];
        int4 da = dv[2 * t], db = dv[2 * t + 1];
        float p0 = d_p[sa.x], p1 = d_p[sa.y], p2 = d_p[sa.z], p3 = d_p[sa.w];
        float p4 = d_p[sb.x], p5 = d_p[sb.y], p6 = d_p[sb.z], p7 = d_p[sb.w];
        atomicAdd(&d_s[da.x], p0);
        atomicAdd(&d_s[da.y], p1);
        atomicAdd(&d_s[da.z], p2);
        atomicAdd(&d_s[da.w], p3);
        atomicAdd(&d_s[db.x], p4);
        atomicAdd(&d_s[db.y], p5);
        atomicAdd(&d_s[db.z], p6);
        atomicAdd(&d_s[db.w], p7);
    }
    int base = E8 << 3;
    int rem = E - base;
    if (t < rem) {
        atomicAdd(&d_s[ei[E + base + t]], d_p[ei[base + t]]);
    }
}

// ---------------------------------------------------------------------------
// K2: fused score + select + pool. RSPLIT blocks per graph; each block
// REDUNDANTLY runs the cheap histogram select in its own smem, then pools
// only its quarter of the rows (atomic accumulate into out).
// Exact lexsort tie semantics (score desc, index asc).
// ---------------------------------------------------------------------------
__global__ void __launch_bounds__(256)
k_rank_pool(const float* __restrict__ x,
            const int* __restrict__ batch,
            const float* __restrict__ b_rel,
            float* __restrict__ out,
            int N) {
    __shared__ unsigned hist[NBINS];
    __shared__ float    sw[MAXSEG];
    __shared__ unsigned chsum[256];
    __shared__ unsigned suf[256];
    __shared__ int s_se[2];
    __shared__ int s_bin, s_m1, s_ncand;
    __shared__ int      cand_idx[MAXSEG];
    __shared__ unsigned cand_key[MAXSEG];
    __shared__ float ps[16][64];

    int g  = blockIdx.x >> 2;
    int sp = blockIdx.x & 3;
    int t = threadIdx.x;

    if (t < 2) s_se[t] = lower_bound_i(batch, N, g + t);
    if (t == 0) { s_bin = -1; s_m1 = 0; s_ncand = 0; }
#pragma unroll
    for (int b = 0; b < CHUNKB; ++b) hist[t * CHUNKB + b] = 0;
    __syncthreads();

    int start = s_se[0];
    int end   = s_se[1];
    int n = end - start;
    int k = (n + 1) >> 1;
    float invk = 1.0f / fmaxf((float)k, 1.0f);
    float bias = b_rel[0];

    if (n <= MAXSEG) {
        // ---- select (duplicated across the RSPLIT blocks of this graph)
        for (int i = t; i < n; i += 256) {
            float sc = tanhf(d_s[start + i] + bias + d_r[start + i]);
            unsigned key = score_key(sc);
            cand_key[i] = key;           // keys by position (temporary)
            atomicAdd(&hist[key >> 21], 1u);
        }
        __syncthreads();

        unsigned cs = 0;
#pragma unroll
        for (int b = 0; b < CHUNKB; ++b) cs += hist[t * CHUNKB + b];
        chsum[t] = cs;
        __syncthreads();

        if (t < 32) {
            unsigned v[8];
            unsigned tot = 0;
#pragma unroll
            for (int j = 7; j >= 0; --j) {
                tot += chsum[t * 8 + j];
                v[j] = tot;
            }
            unsigned run = tot;
#pragma unroll
            for (int off = 1; off < 32; off <<= 1) {
                unsigned q = __shfl_down_sync(0xffffffffu, run, off);
                if (t + off < 32) run += q;
            }
            unsigned tail = run - tot;
#pragma unroll
            for (int j = 0; j < 8; ++j) suf[t * 8 + j] = v[j] + tail;
        }
        __syncthreads();

        {
            unsigned above = suf[t] - chsum[t];
            if ((int)above < k && k <= (int)suf[t]) {
                int acc = (int)above;
                for (int b = CHUNKB - 1; b >= 0; --b) {
                    int h = (int)hist[t * CHUNKB + b];
                    if (acc < k && k <= acc + h) { s_bin = t * CHUNKB + b; s_m1 = acc; }
                    acc += h;
                }
            }
        }
        __syncthreads();

        int binb = s_bin, m1 = s_m1;
        for (int i = t; i < n; i += 256) {
            unsigned key = cand_key[i];
            int bin = (int)(key >> 21);
            if (bin > binb) {
                sw[i] = key_score(key) * invk;
            } else if (bin < binb) {
                sw[i] = 0.0f;
            } else {
                int c = atomicAdd(&s_ncand, 1);
                cand_idx[c] = i;
            }
        }
        __syncthreads();
        int nc = s_ncand;
        unsigned mykey[4];
        int myidx[4];
        int mycnt = 0;
        for (int c = t; c < nc; c += 256) {
            myidx[mycnt] = cand_idx[c];
            mykey[mycnt] = cand_key[cand_idx[c]];
            ++mycnt;
        }
        __syncthreads();
        for (int c = t, m = 0; c < nc; c += 256, ++m) cand_key[c] = mykey[m];
        __syncthreads();

        int r = k - m1;
        for (int c = t, m = 0; c < nc; c += 256, ++m) {
            unsigned ki = mykey[m];
            int ii = myidx[m];
            int cnt = 0;
            for (int j = 0; j < nc; ++j) {
                unsigned kj = cand_key[j];
                cnt += (kj > ki) || (kj == ki && cand_idx[j] < ii);
            }
            sw[ii] = (cnt < r) ? key_score(ki) * invk : 0.0f;
        }
        __syncthreads();

        // ---- pool this block's quarter (dense branch-free stream)
        int chunk = (n + RSPLIT - 1) / RSPLIT;
        int i0 = sp * chunk;
        int i1 = i0 + chunk; if (i1 > n) i1 = n;
        int q  = t & 15;
        int rg = t >> 4;
        const float4* xv = (const float4*)x;
        float4 acc = make_float4(0.f, 0.f, 0.f, 0.f);
#pragma unroll 4
        for (int i = i0 + rg; i < i1; i += 16) {
            float w  = sw[i];
            float4 v = xv[(size_t)(start + i) * 16 + q];
            acc.x += w * v.x; acc.y += w * v.y;
            acc.z += w * v.z; acc.w += w * v.w;
        }
        ps[rg][q * 4 + 0] = acc.x;
        ps[rg][q * 4 + 1] = acc.y;
        ps[rg][q * 4 + 2] = acc.z;
        ps[rg][q * 4 + 3] = acc.w;
        __syncthreads();
        if (t < 64) {
            float v = 0.0f;
#pragma unroll
            for (int j = 0; j < 16; ++j) v += ps[j][t];
            if (v != 0.0f) atomicAdd(&out[g * 64 + t], v);
        }
    } else {
        // ---- improbable fallback: global O(n^2) select (sp 0 writes d_w),
        //      then all splits pool their quarter from d_w.
        if (sp == 0) {
            for (int i = t; i < n; i += 256)
                d_score[start + i] = tanhf(d_s[start + i] + bias + d_r[start + i]);
            __syncthreads();
            for (int i = t; i < n; i += 256) {
                float si = d_score[start + i];
                int cnt = 0;
                for (int j = 0; j < i; ++j)     cnt += (d_score[start + j] >= si);
                for (int j = i + 1; j < n; ++j) cnt += (d_score[start + j] >  si);
                d_w[start + i] = (cnt < k) ? si * invk : 0.0f;
            }
            __syncthreads();
            int q  = t & 15;
            int rg = t >> 4;
            const float4* xv = (const float4*)x;
            float4 acc = make_float4(0.f, 0.f, 0.f, 0.f);
            for (int i = rg; i < n; i += 16) {
                float w  = d_w[start + i];
                float4 v = xv[(size_t)(start + i) * 16 + q];
                acc.x += w * v.x; acc.y += w * v.y;
                acc.z += w * v.z; acc.w += w * v.w;
            }
            ps[rg][q * 4 + 0] = acc.x;
            ps[rg][q * 4 + 1] = acc.y;
            ps[rg][q * 4 + 2] = acc.z;
            ps[rg][q * 4 + 3] = acc.w;
            __syncthreads();
            if (t < 64) {
                float v = 0.0f;
#pragma unroll
                for (int j = 0; j < 16; ++j) v += ps[j][t];
                if (v != 0.0f) atomicAdd(&out[g * 64 + t], v);
            }
        }
    }
}

// ---------------------------------------------------------------------------
extern "C" void kernel_launch(void* const* d_in, const int* in_sizes, int n_in,
                              void* d_out, int out_size) {
    const float* x      = (const float*)d_in[0];
    const int*   ei     = (const int*)d_in[1];
    const int*   batch  = (const int*)d_in[2];
    const float* w_rel  = (const float*)d_in[3];
    const float* b_rel  = (const float*)d_in[4];
    const float* w_root = (const float*)d_in[5];
    float*       out    = (float*)d_out;

    int N = in_sizes[2];
    int E = in_sizes[1] / 2;

    {
        long long threads = (long long)N * 8;
        int blocks = (int)((threads + 255) / 256);
        k_node_dots<<<blocks, 256>>>(x, w_rel, w_root, out, N);
    }
    {
        int E8 = E >> 3;
        int work = E8 > 8 ? E8 : 8;     // cover tail even when E8 == 0
        k_edge_scatter<<<(work + 255) / 256, 256>>>(ei, E);
    }
    k_rank_pool<<<NGRAPH * RSPLIT, 256>>>(x, batch, b_rel, out, N);
}

// round 13
// speedup vs baseline: 1.1757x; 1.1757x over previous
#include <cuda_runtime.h>
#include <math.h>

#define MAX_N    131072
#define NGRAPH   256
#define MAXSEG   1024
#define NBINS    2048
#define RPT      512     // rank_pool threads
#define CHUNKB   4       // bins per thread (2048/512)

// Scratch (static __device__ arrays — no allocation allowed)
__device__ float d_p[MAX_N];        // x[i] . w_rel
__device__ float d_r[MAX_N];        // x[i] . w_root
__device__ float d_s[MAX_N];        // segment-summed p over edges
__device__ float d_score[MAX_N];    // fallback scratch only
__device__ float d_w[MAX_N];        // fallback scratch only
__device__ int   d_starts[NGRAPH + 1];

__device__ __forceinline__ unsigned score_key(float s) {
    unsigned u = __float_as_uint(s);
    return (u & 0x80000000u) ? ~u : (u | 0x80000000u);   // monotone
}
__device__ __forceinline__ float key_score(unsigned k) {
    return (k & 0x80000000u) ? __uint_as_float(k & 0x7fffffffu)
                             : __uint_as_float(~k);
}
__device__ __forceinline__ float dot4(float4 a, float4 b) {
    return a.x * b.x + a.y * b.y + a.z * b.z + a.w * b.w;
}

// ---------------------------------------------------------------------------
// K0: per-node dots (8 threads/node, 2x float4); zero s; zero out;
// segment-start detection on sorted batch.
// ---------------------------------------------------------------------------
__global__ void k_node_dots(const float* __restrict__ x,
                            const float* __restrict__ w_rel,
                            const float* __restrict__ w_root,
                            const int* __restrict__ batch,
                            float* __restrict__ out,
                            int N) {
    int gid = blockIdx.x * blockDim.x + threadIdx.x;
    if (gid < NGRAPH * 64) out[gid] = 0.0f;
    int node = gid >> 3;
    if (node >= N) return;
    int sub = gid & 7;
    const float4* xr = (const float4*)(x + (size_t)node * 64);
    float4 v0 = xr[sub];
    float4 v1 = xr[sub + 8];
    const float4* wrv = (const float4*)w_rel;
    const float4* wtv = (const float4*)w_root;
    float a = dot4(v0, wrv[sub]) + dot4(v1, wrv[sub + 8]);
    float b = dot4(v0, wtv[sub]) + dot4(v1, wtv[sub + 8]);
#pragma unroll
    for (int o = 4; o; o >>= 1) {
        a += __shfl_xor_sync(0xffffffffu, a, o);
        b += __shfl_xor_sync(0xffffffffu, b, o);
    }
    if (sub == 0) {
        d_p[node] = a;
        d_r[node] = b;
        d_s[node] = 0.0f;
        // segment starts of the sorted batch array
        int bi = batch[node];
        if (node == 0) {
            for (int g = 0; g <= bi; ++g) d_starts[g] = 0;
        } else {
            int bp = batch[node - 1];
            for (int g = bp + 1; g <= bi; ++g) d_starts[g] = node;
        }
        if (node == N - 1) {
            for (int g = bi + 1; g <= NGRAPH; ++g) d_starts[g] = N;
        }
    }
}

// ---------------------------------------------------------------------------
// K1: edge scatter  s[dst] += p[src].  8 edges/thread; tail folded in.
// ---------------------------------------------------------------------------
__global__ void k_edge_scatter(const int* __restrict__ ei, int E) {
    int t = blockIdx.x * blockDim.x + threadIdx.x;
    int E8 = E >> 3;
    if (t < E8) {
        const int4* sv = (const int4*)ei;
        const int4* dv = (const int4*)(ei + E);
        int4 sa = sv[2 * t], sb = sv[2 * t + 1];
        int4 da = dv[2 * t], db = dv[2 * t + 1];
        float p0 = d_p[sa.x], p1 = d_p[sa.y], p2 = d_p[sa.z], p3 = d_p[sa.w];
        float p4 = d_p[sb.x], p5 = d_p[sb.y], p6 = d_p[sb.z], p7 = d_p[sb.w];
        atomicAdd(&d_s[da.x], p0);
        atomicAdd(&d_s[da.y], p1);
        atomicAdd(&d_s[da.z], p2);
        atomicAdd(&d_s[da.w], p3);
        atomicAdd(&d_s[db.x], p4);
        atomicAdd(&d_s[db.y], p5);
        atomicAdd(&d_s[db.z], p6);
        atomicAdd(&d_s[db.w], p7);
    }
    int base = E8 << 3;
    int rem = E - base;
    if (t < rem) {
        atomicAdd(&d_s[ei[E + base + t]], d_p[ei[base + t]]);
    }
}

// ---------------------------------------------------------------------------
// K2: fused per-graph score + histogram top-k select + weighted mean pool.
// 512 threads, one block per graph, starts precomputed. Exact lexsort ties.
// ---------------------------------------------------------------------------
__global__ void __launch_bounds__(RPT)
k_rank_pool(const float* __restrict__ x,
            const float* __restrict__ b_rel,
            float* __restrict__ out) {
    __shared__ unsigned hist[NBINS];
    __shared__ float    sw[MAXSEG];
    __shared__ unsigned chsum[RPT];
    __shared__ unsigned suf[RPT];
    __shared__ int s_bin, s_m1, s_ncand;
    __shared__ int      cand_idx[MAXSEG];
    __shared__ unsigned cand_key[MAXSEG];
    __shared__ float ps[32][64];

    int g = blockIdx.x;
    int t = threadIdx.x;

    if (t == 0) { s_bin = -1; s_m1 = 0; s_ncand = 0; }
#pragma unroll
    for (int b = 0; b < CHUNKB; ++b) hist[t * CHUNKB + b] = 0;

    int start = d_starts[g];
    int end   = d_starts[g + 1];
    int n = end - start;
    int k = (n + 1) >> 1;
    float invk = 1.0f / fmaxf((float)k, 1.0f);
    float bias = b_rel[0];
    __syncthreads();

    if (n <= MAXSEG) {
        // ---- phase 1: keys + histogram (keys by position in cand_key)
        for (int i = t; i < n; i += RPT) {
            float sc = tanhf(d_s[start + i] + bias + d_r[start + i]);
            unsigned key = score_key(sc);
            cand_key[i] = key;
            atomicAdd(&hist[key >> 21], 1u);
        }
        __syncthreads();

        unsigned cs = 0;
#pragma unroll
        for (int b = 0; b < CHUNKB; ++b) cs += hist[t * CHUNKB + b];
        chsum[t] = cs;
        __syncthreads();

        // single-warp suffix scan over 512 chunk sums (16 per lane)
        if (t < 32) {
            unsigned v[16];
            unsigned tot = 0;
#pragma unroll
            for (int j = 15; j >= 0; --j) {
                tot += chsum[t * 16 + j];
                v[j] = tot;
            }
            unsigned run = tot;
#pragma unroll
            for (int off = 1; off < 32; off <<= 1) {
                unsigned q = __shfl_down_sync(0xffffffffu, run, off);
                if (t + off < 32) run += q;
            }
            unsigned tail = run - tot;
#pragma unroll
            for (int j = 0; j < 16; ++j) suf[t * 16 + j] = v[j] + tail;
        }
        __syncthreads();

        {
            unsigned above = suf[t] - chsum[t];
            if ((int)above < k && k <= (int)suf[t]) {
                int acc = (int)above;
                for (int b = CHUNKB - 1; b >= 0; --b) {
                    int h = (int)hist[t * CHUNKB + b];
                    if (acc < k && k <= acc + h) { s_bin = t * CHUNKB + b; s_m1 = acc; }
                    acc += h;
                }
            }
        }
        __syncthreads();

        int binb = s_bin, m1 = s_m1;
        // ---- phase 2: classify into sw; threshold bin -> candidates
        for (int i = t; i < n; i += RPT) {
            unsigned key = cand_key[i];
            int bin = (int)(key >> 21);
            if (bin > binb) {
                sw[i] = key_score(key) * invk;
            } else if (bin < binb) {
                sw[i] = 0.0f;
            } else {
                int c = atomicAdd(&s_ncand, 1);
                cand_idx[c] = i;
            }
        }
        __syncthreads();
        int nc = s_ncand;
        unsigned mykey[2];
        int myidx[2];
        int mycnt = 0;
        for (int c = t; c < nc; c += RPT) {
            myidx[mycnt] = cand_idx[c];
            mykey[mycnt] = cand_key[cand_idx[c]];
            ++mycnt;
        }
        __syncthreads();
        for (int c = t, m = 0; c < nc; c += RPT, ++m) cand_key[c] = mykey[m];
        __syncthreads();

        int r = k - m1;
        for (int c = t, m = 0; c < nc; c += RPT, ++m) {
            unsigned ki = mykey[m];
            int ii = myidx[m];
            int cnt = 0;
            for (int j = 0; j < nc; ++j) {
                unsigned kj = cand_key[j];
                cnt += (kj > ki) || (kj == ki && cand_idx[j] < ii);
            }
            sw[ii] = (cnt < r) ? key_score(ki) * invk : 0.0f;
        }
        __syncthreads();

        // ---- phase 3: pool (dense branch-free stream, weights from smem)
        int q  = t & 15;        // col quad
        int rg = t >> 4;        // row group (32)
        const float4* xv = (const float4*)x;
        float4 acc = make_float4(0.f, 0.f, 0.f, 0.f);
#pragma unroll 4
        for (int i = rg; i < n; i += 32) {
            float w  = sw[i];
            float4 v = xv[(size_t)(start + i) * 16 + q];
            acc.x += w * v.x; acc.y += w * v.y;
            acc.z += w * v.z; acc.w += w * v.w;
        }
        ps[rg][q * 4 + 0] = acc.x;
        ps[rg][q * 4 + 1] = acc.y;
        ps[rg][q * 4 + 2] = acc.z;
        ps[rg][q * 4 + 3] = acc.w;
        __syncthreads();
        if (t < 64) {
            float v = 0.0f;
#pragma unroll
            for (int j = 0; j < 32; ++j) v += ps[j][t];
            out[g * 64 + t] = v;
        }
    } else {
        // ---- improbable fallback: global O(n^2) + pool from d_w
        for (int i = t; i < n; i += RPT)
            d_score[start + i] = tanhf(d_s[start + i] + bias + d_r[start + i]);
        __syncthreads();
        for (int i = t; i < n; i += RPT) {
            float si = d_score[start + i];
            int cnt = 0;
            for (int j = 0; j < i; ++j)     cnt += (d_score[start + j] >= si);
            for (int j = i + 1; j < n; ++j) cnt += (d_score[start + j] >  si);
            d_w[start + i] = (cnt < k) ? si * invk : 0.0f;
        }
        __syncthreads();
        int q  = t & 15;
        int rg = t >> 4;
        const float4* xv = (const float4*)x;
        float4 acc = make_float4(0.f, 0.f, 0.f, 0.f);
        for (int i = rg; i < n; i += 32) {
            float w  = d_w[start + i];
            float4 v = xv[(size_t)(start + i) * 16 + q];
            acc.x += w * v.x; acc.y += w * v.y;
            acc.z += w * v.z; acc.w += w * v.w;
        }
        ps[rg][q * 4 + 0] = acc.x;
        ps[rg][q * 4 + 1] = acc.y;
        ps[rg][q * 4 + 2] = acc.z;
        ps[rg][q * 4 + 3] = acc.w;
        __syncthreads();
        if (t < 64) {
            float v = 0.0f;
#pragma unroll
            for (int j = 0; j < 32; ++j) v += ps[j][t];
            out[g * 64 + t] = v;
        }
    }
}

// ---------------------------------------------------------------------------
extern "C" void kernel_launch(void* const* d_in, const int* in_sizes, int n_in,
                              void* d_out, int out_size) {
    const float* x      = (const float*)d_in[0];
    const int*   ei     = (const int*)d_in[1];
    const int*   batch  = (const int*)d_in[2];
    const float* w_rel  = (const float*)d_in[3];
    const float* b_rel  = (const float*)d_in[4];
    const float* w_root = (const float*)d_in[5];
    float*       out    = (float*)d_out;

    int N = in_sizes[2];
    int E = in_sizes[1] / 2;

    {
        long long threads = (long long)N * 8;
        int blocks = (int)((threads + 255) / 256);
        k_node_dots<<<blocks, 256>>>(x, w_rel, w_root, batch, out, N);
    }
    {
        int E8 = E >> 3;
        int work = E8 > 8 ? E8 : 8;     // cover tail even when E8 == 0
        k_edge_scatter<<<(work + 255) / 256, 256>>>(ei, E);
    }
    k_rank_pool<<<NGRAPH, RPT>>>(x, b_rel, out);
}

// round 14
// speedup vs baseline: 1.1837x; 1.0067x over previous
#include <cuda_runtime.h>
#include <math.h>

#define MAX_N    131072
#define NGRAPH   256
#define MAXSEG   1024
#define NBINS    2048
#define RPT      512     // rank_pool threads
#define CHUNKB   4       // bins per thread (2048/512)

// Scratch (static __device__ arrays — no allocation allowed)
__device__ float d_p[MAX_N];        // x[i] . w_rel
__device__ float d_r[MAX_N];        // x[i] . w_root
__device__ float d_s[MAX_N];        // segment-summed p over edges
__device__ float d_score[MAX_N];    // fallback scratch only
__device__ float d_w[MAX_N];        // fallback scratch only
__device__ int   d_starts[NGRAPH + 1];

__device__ __forceinline__ unsigned score_key(float s) {
    unsigned u = __float_as_uint(s);
    return (u & 0x80000000u) ? ~u : (u | 0x80000000u);   // monotone
}
__device__ __forceinline__ float key_score(unsigned k) {
    return (k & 0x80000000u) ? __uint_as_float(k & 0x7fffffffu)
                             : __uint_as_float(~k);
}
__device__ __forceinline__ float dot4(float4 a, float4 b) {
    return a.x * b.x + a.y * b.y + a.z * b.z + a.w * b.w;
}

// ---------------------------------------------------------------------------
// K0: per-node dots (8 threads/node). Weights staged in smem (2 LDG + 4 LDS
// per thread instead of 6 LDG -> fewer LSU issue slots). Zero s; zero out;
// segment-start detection on sorted batch.
// ---------------------------------------------------------------------------
__global__ void k_node_dots(const float* __restrict__ x,
                            const float* __restrict__ w_rel,
                            const float* __restrict__ w_root,
                            const int* __restrict__ batch,
                            float* __restrict__ out,
                            int N) {
    __shared__ float4 swt[32];      // [0..15] w_rel, [16..31] w_root
    int tid = threadIdx.x;
    if (tid < 32) {
        swt[tid] = (tid < 16) ? ((const float4*)w_rel)[tid]
                              : ((const float4*)w_root)[tid - 16];
    }
    __syncthreads();

    int gid = blockIdx.x * blockDim.x + tid;
    if (gid < NGRAPH * 64) out[gid] = 0.0f;
    int node = gid >> 3;
    if (node >= N) return;
    int sub = gid & 7;
    const float4* xr = (const float4*)(x + (size_t)node * 64);
    float4 v0 = xr[sub];
    float4 v1 = xr[sub + 8];
    float a = dot4(v0, swt[sub])      + dot4(v1, swt[sub + 8]);
    float b = dot4(v0, swt[16 + sub]) + dot4(v1, swt[24 + sub]);
#pragma unroll
    for (int o = 4; o; o >>= 1) {
        a += __shfl_xor_sync(0xffffffffu, a, o);
        b += __shfl_xor_sync(0xffffffffu, b, o);
    }
    if (sub == 0) {
        d_p[node] = a;
        d_r[node] = b;
        d_s[node] = 0.0f;
        // segment starts of the sorted batch array
        int bi = batch[node];
        if (node == 0) {
            for (int g = 0; g <= bi; ++g) d_starts[g] = 0;
        } else {
            int bp = batch[node - 1];
            for (int g = bp + 1; g <= bi; ++g) d_starts[g] = node;
        }
        if (node == N - 1) {
            for (int g = bi + 1; g <= NGRAPH; ++g) d_starts[g] = N;
        }
    }
}

// ---------------------------------------------------------------------------
// K1: edge scatter  s[dst] += p[src].  8 edges/thread; tail folded in.
// ---------------------------------------------------------------------------
__global__ void k_edge_scatter(const int* __restrict__ ei, int E) {
    int t = blockIdx.x * blockDim.x + threadIdx.x;
    int E8 = E >> 3;
    if (t < E8) {
        const int4* sv = (const int4*)ei;
        const int4* dv = (const int4*)(ei + E);
        int4 sa = sv[2 * t], sb = sv[2 * t + 1];
        int4 da = dv[2 * t], db = dv[2 * t + 1];
        float p0 = d_p[sa.x], p1 = d_p[sa.y], p2 = d_p[sa.z], p3 = d_p[sa.w];
        float p4 = d_p[sb.x], p5 = d_p[sb.y], p6 = d_p[sb.z], p7 = d_p[sb.w];
        atomicAdd(&d_s[da.x], p0);
        atomicAdd(&d_s[da.y], p1);
        atomicAdd(&d_s[da.z], p2);
        atomicAdd(&d_s[da.w], p3);
        atomicAdd(&d_s[db.x], p4);
        atomicAdd(&d_s[db.y], p5);
        atomicAdd(&d_s[db.z], p6);
        atomicAdd(&d_s[db.w], p7);
    }
    int base = E8 << 3;
    int rem = E - base;
    if (t < rem) {
        atomicAdd(&d_s[ei[E + base + t]], d_p[ei[base + t]]);
    }
}

// ---------------------------------------------------------------------------
// K2: fused per-graph score + histogram top-k select + weighted mean pool.
// 512 threads, one block per graph, starts precomputed. Exact lexsort ties.
// ---------------------------------------------------------------------------
__global__ void __launch_bounds__(RPT)
k_rank_pool(const float* __restrict__ x,
            const float* __restrict__ b_rel,
            float* __restrict__ out) {
    __shared__ unsigned hist[NBINS];
    __shared__ float    sw[MAXSEG];
    __shared__ unsigned chsum[RPT];
    __shared__ unsigned suf[RPT];
    __shared__ int s_bin, s_m1, s_ncand;
    __shared__ int      cand_idx[MAXSEG];
    __shared__ unsigned cand_key[MAXSEG];
    __shared__ float ps[32][64];

    int g = blockIdx.x;
    int t = threadIdx.x;

    if (t == 0) { s_bin = -1; s_m1 = 0; s_ncand = 0; }
#pragma unroll
    for (int b = 0; b < CHUNKB; ++b) hist[t * CHUNKB + b] = 0;

    int start = d_starts[g];
    int end   = d_starts[g + 1];
    int n = end - start;
    int k = (n + 1) >> 1;
    float invk = 1.0f / fmaxf((float)k, 1.0f);
    float bias = b_rel[0];
    __syncthreads();

    if (n <= MAXSEG) {
        // ---- phase 1: keys + histogram (keys by position in cand_key)
        for (int i = t; i < n; i += RPT) {
            float sc = tanhf(d_s[start + i] + bias + d_r[start + i]);
            unsigned key = score_key(sc);
            cand_key[i] = key;
            atomicAdd(&hist[key >> 21], 1u);
        }
        __syncthreads();

        unsigned cs = 0;
#pragma unroll
        for (int b = 0; b < CHUNKB; ++b) cs += hist[t * CHUNKB + b];
        chsum[t] = cs;
        __syncthreads();

        // single-warp suffix scan over 512 chunk sums (16 per lane)
        if (t < 32) {
            unsigned v[16];
            unsigned tot = 0;
#pragma unroll
            for (int j = 15; j >= 0; --j) {
                tot += chsum[t * 16 + j];
                v[j] = tot;
            }
            unsigned run = tot;
#pragma unroll
            for (int off = 1; off < 32; off <<= 1) {
                unsigned q = __shfl_down_sync(0xffffffffu, run, off);
                if (t + off < 32) run += q;
            }
            unsigned tail = run - tot;
#pragma unroll
            for (int j = 0; j < 16; ++j) suf[t * 16 + j] = v[j] + tail;
        }
        __syncthreads();

        {
            unsigned above = suf[t] - chsum[t];
            if ((int)above < k && k <= (int)suf[t]) {
                int acc = (int)above;
                for (int b = CHUNKB - 1; b >= 0; --b) {
                    int h = (int)hist[t * CHUNKB + b];
                    if (acc < k && k <= acc + h) { s_bin = t * CHUNKB + b; s_m1 = acc; }
                    acc += h;
                }
            }
        }
        __syncthreads();

        int binb = s_bin, m1 = s_m1;
        // ---- phase 2: classify into sw; threshold bin -> candidates
        for (int i = t; i < n; i += RPT) {
            unsigned key = cand_key[i];
            int bin = (int)(key >> 21);
            if (bin > binb) {
                sw[i] = key_score(key) * invk;
            } else if (bin < binb) {
                sw[i] = 0.0f;
            } else {
                int c = atomicAdd(&s_ncand, 1);
                cand_idx[c] = i;
            }
        }
        __syncthreads();
        int nc = s_ncand;
        unsigned mykey[2];
        int myidx[2];
        int mycnt = 0;
        for (int c = t; c < nc; c += RPT) {
            myidx[mycnt] = cand_idx[c];
            mykey[mycnt] = cand_key[cand_idx[c]];
            ++mycnt;
        }
        __syncthreads();
        for (int c = t, m = 0; c < nc; c += RPT, ++m) cand_key[c] = mykey[m];
        __syncthreads();

        int r = k - m1;
        for (int c = t, m = 0; c < nc; c += RPT, ++m) {
            unsigned ki = mykey[m];
            int ii = myidx[m];
            int cnt = 0;
            for (int j = 0; j < nc; ++j) {
                unsigned kj = cand_key[j];
                cnt += (kj > ki) || (kj == ki && cand_idx[j] < ii);
            }
            sw[ii] = (cnt < r) ? key_score(ki) * invk : 0.0f;
        }
        __syncthreads();

        // ---- phase 3: pool (dense branch-free stream, weights from smem)
        int q  = t & 15;        // col quad
        int rg = t >> 4;        // row group (32)
        const float4* xv = (const float4*)x;
        float4 acc = make_float4(0.f, 0.f, 0.f, 0.f);
#pragma unroll 4
        for (int i = rg; i < n; i += 32) {
            float w  = sw[i];
            float4 v = xv[(size_t)(start + i) * 16 + q];
            acc.x += w * v.x; acc.y += w * v.y;
            acc.z += w * v.z; acc.w += w * v.w;
        }
        ps[rg][q * 4 + 0] = acc.x;
        ps[rg][q * 4 + 1] = acc.y;
        ps[rg][q * 4 + 2] = acc.z;
        ps[rg][q * 4 + 3] = acc.w;
        __syncthreads();
        if (t < 64) {
            float v = 0.0f;
#pragma unroll
            for (int j = 0; j < 32; ++j) v += ps[j][t];
            out[g * 64 + t] = v;
        }
    } else {
        // ---- improbable fallback: global O(n^2) + pool from d_w
        for (int i = t; i < n; i += RPT)
            d_score[start + i] = tanhf(d_s[start + i] + bias + d_r[start + i]);
        __syncthreads();
        for (int i = t; i < n; i += RPT) {
            float si = d_score[start + i];
            int cnt = 0;
            for (int j = 0; j < i; ++j)     cnt += (d_score[start + j] >= si);
            for (int j = i + 1; j < n; ++j) cnt += (d_score[start + j] >  si);
            d_w[start + i] = (cnt < k) ? si * invk : 0.0f;
        }
        __syncthreads();
        int q  = t & 15;
        int rg = t >> 4;
        const float4* xv = (const float4*)x;
        float4 acc = make_float4(0.f, 0.f, 0.f, 0.f);
        for (int i = rg; i < n; i += 32) {
            float w  = d_w[start + i];
            float4 v = xv[(size_t)(start + i) * 16 + q];
            acc.x += w * v.x; acc.y += w * v.y;
            acc.z += w * v.z; acc.w += w * v.w;
        }
        ps[rg][q * 4 + 0] = acc.x;
        ps[rg][q * 4 + 1] = acc.y;
        ps[rg][q * 4 + 2] = acc.z;
        ps[rg][q * 4 + 3] = acc.w;
        __syncthreads();
        if (t < 64) {
            float v = 0.0f;
#pragma unroll
            for (int j = 0; j < 32; ++j) v += ps[j][t];
            out[g * 64 + t] = v;
        }
    }
}

// ---------------------------------------------------------------------------
extern "C" void kernel_launch(void* const* d_in, const int* in_sizes, int n_in,
                              void* d_out, int out_size) {
    const float* x      = (const float*)d_in[0];
    const int*   ei     = (const int*)d_in[1];
    const int*   batch  = (const int*)d_in[2];
    const float* w_rel  = (const float*)d_in[3];
    const float* b_rel  = (const float*)d_in[4];
    const float* w_root = (const float*)d_in[5];
    float*       out    = (float*)d_out;

    int N = in_sizes[2];
    int E = in_sizes[1] / 2;

    {
        long long threads = (long long)N * 8;
        int blocks = (int)((threads + 255) / 256);
        k_node_dots<<<blocks, 256>>>(x, w_rel, w_root, batch, out, N);
    }
    {
        int E8 = E >> 3;
        int work = E8 > 8 ? E8 : 8;     // cover tail even when E8 == 0
        k_edge_scatter<<<(work + 255) / 256, 256>>>(ei, E);
    }
    k_rank_pool<<<NGRAPH, RPT>>>(x, b_rel, out);
}

// round 15
// speedup vs baseline: 1.1963x; 1.0107x over previous
#include <cuda_runtime.h>
#include <math.h>

#define MAX_N    131072
#define NGRAPH   256
#define MAXSEG   1024
#define NBINS    2048
#define RPT      512     // rank_pool threads
#define CHUNKB   4       // bins per thread (2048/512)

// Scratch (static __device__ arrays — no allocation allowed)
__device__ float d_p[MAX_N];        // x[i] . w_rel
__device__ float d_r[MAX_N];        // x[i] . w_root
__device__ float d_s[MAX_N];        // segment-summed p over edges
__device__ float d_score[MAX_N];    // fallback scratch only
__device__ float d_w[MAX_N];        // fallback scratch only
__device__ int   d_starts[NGRAPH + 1];

__device__ __forceinline__ unsigned score_key(float s) {
    unsigned u = __float_as_uint(s);
    return (u & 0x80000000u) ? ~u : (u | 0x80000000u);   // monotone
}
__device__ __forceinline__ float key_score(unsigned k) {
    return (k & 0x80000000u) ? __uint_as_float(k & 0x7fffffffu)
                             : __uint_as_float(~k);
}
__device__ __forceinline__ float dot4(float4 a, float4 b) {
    return a.x * b.x + a.y * b.y + a.z * b.z + a.w * b.w;
}

// ---------------------------------------------------------------------------
// K0: per-node dots (8 threads/node, 2x float4); zero s; zero out;
// segment-start detection on sorted batch. (R13 form — best measured.)
// ---------------------------------------------------------------------------
__global__ void k_node_dots(const float* __restrict__ x,
                            const float* __restrict__ w_rel,
                            const float* __restrict__ w_root,
                            const int* __restrict__ batch,
                            float* __restrict__ out,
                            int N) {
    int gid = blockIdx.x * blockDim.x + threadIdx.x;
    if (gid < NGRAPH * 64) out[gid] = 0.0f;
    int node = gid >> 3;
    if (node >= N) return;
    int sub = gid & 7;
    const float4* xr = (const float4*)(x + (size_t)node * 64);
    float4 v0 = xr[sub];
    float4 v1 = xr[sub + 8];
    const float4* wrv = (const float4*)w_rel;
    const float4* wtv = (const float4*)w_root;
    float a = dot4(v0, wrv[sub]) + dot4(v1, wrv[sub + 8]);
    float b = dot4(v0, wtv[sub]) + dot4(v1, wtv[sub + 8]);
#pragma unroll
    for (int o = 4; o; o >>= 1) {
        a += __shfl_xor_sync(0xffffffffu, a, o);
        b += __shfl_xor_sync(0xffffffffu, b, o);
    }
    if (sub == 0) {
        d_p[node] = a;
        d_r[node] = b;
        d_s[node] = 0.0f;
        int bi = batch[node];
        if (node == 0) {
            for (int g = 0; g <= bi; ++g) d_starts[g] = 0;
        } else {
            int bp = batch[node - 1];
            for (int g = bp + 1; g <= bi; ++g) d_starts[g] = node;
        }
        if (node == N - 1) {
            for (int g = bi + 1; g <= NGRAPH; ++g) d_starts[g] = N;
        }
    }
}

// ---------------------------------------------------------------------------
// K1: edge scatter  s[dst] += p[src].  8 edges/thread; streaming ei loads
// (read-once, keep x resident in L2); tail folded in.
// ---------------------------------------------------------------------------
__global__ void k_edge_scatter(const int* __restrict__ ei, int E) {
    int t = blockIdx.x * blockDim.x + threadIdx.x;
    int E8 = E >> 3;
    if (t < E8) {
        const int4* sv = (const int4*)ei;
        const int4* dv = (const int4*)(ei + E);
        int4 sa = __ldcs(&sv[2 * t]);
        int4 sb = __ldcs(&sv[2 * t + 1]);
        int4 da = __ldcs(&dv[2 * t]);
        int4 db = __ldcs(&dv[2 * t + 1]);
        float p0 = d_p[sa.x], p1 = d_p[sa.y], p2 = d_p[sa.z], p3 = d_p[sa.w];
        float p4 = d_p[sb.x], p5 = d_p[sb.y], p6 = d_p[sb.z], p7 = d_p[sb.w];
        atomicAdd(&d_s[da.x], p0);
        atomicAdd(&d_s[da.y], p1);
        atomicAdd(&d_s[da.z], p2);
        atomicAdd(&d_s[da.w], p3);
        atomicAdd(&d_s[db.x], p4);
        atomicAdd(&d_s[db.y], p5);
        atomicAdd(&d_s[db.z], p6);
        atomicAdd(&d_s[db.w], p7);
    }
    int base = E8 << 3;
    int rem = E - base;
    if (t < rem) {
        atomicAdd(&d_s[__ldcs(&ei[E + base + t])], d_p[__ldcs(&ei[base + t])]);
    }
}

// ---------------------------------------------------------------------------
// K2: fused per-graph score + histogram top-k select + weighted mean pool.
// 512 threads, one block per graph, starts precomputed. Exact lexsort ties.
// ---------------------------------------------------------------------------
__global__ void __launch_bounds__(RPT)
k_rank_pool(const float* __restrict__ x,
            const float* __restrict__ b_rel,
            float* __restrict__ out) {
    __shared__ unsigned hist[NBINS];
    __shared__ float    sw[MAXSEG];
    __shared__ unsigned chsum[RPT];
    __shared__ unsigned suf[RPT];
    __shared__ int s_bin, s_m1, s_ncand;
    __shared__ int      cand_idx[MAXSEG];
    __shared__ unsigned cand_key[MAXSEG];
    __shared__ float ps[32][64];

    int g = blockIdx.x;
    int t = threadIdx.x;

    if (t == 0) { s_bin = -1; s_m1 = 0; s_ncand = 0; }
#pragma unroll
    for (int b = 0; b < CHUNKB; ++b) hist[t * CHUNKB + b] = 0;

    int start = d_starts[g];
    int end   = d_starts[g + 1];
    int n = end - start;
    int k = (n + 1) >> 1;
    float invk = 1.0f / fmaxf((float)k, 1.0f);
    float bias = b_rel[0];
    __syncthreads();

    if (n <= MAXSEG) {
        // ---- phase 1: keys + histogram (keys by position in cand_key)
        for (int i = t; i < n; i += RPT) {
            float sc = tanhf(d_s[start + i] + bias + d_r[start + i]);
            unsigned key = score_key(sc);
            cand_key[i] = key;
            atomicAdd(&hist[key >> 21], 1u);
        }
        __syncthreads();

        unsigned cs = 0;
#pragma unroll
        for (int b = 0; b < CHUNKB; ++b) cs += hist[t * CHUNKB + b];
        chsum[t] = cs;
        __syncthreads();

        // single-warp suffix scan over 512 chunk sums (16 per lane)
        if (t < 32) {
            unsigned v[16];
            unsigned tot = 0;
#pragma unroll
            for (int j = 15; j >= 0; --j) {
                tot += chsum[t * 16 + j];
                v[j] = tot;
            }
            unsigned run = tot;
#pragma unroll
            for (int off = 1; off < 32; off <<= 1) {
                unsigned q = __shfl_down_sync(0xffffffffu, run, off);
                if (t + off < 32) run += q;
            }
            unsigned tail = run - tot;
#pragma unroll
            for (int j = 0; j < 16; ++j) suf[t * 16 + j] = v[j] + tail;
        }
        __syncthreads();

        {
            unsigned above = suf[t] - chsum[t];
            if ((int)above < k && k <= (int)suf[t]) {
                int acc = (int)above;
                for (int b = CHUNKB - 1; b >= 0; --b) {
                    int h = (int)hist[t * CHUNKB + b];
                    if (acc < k && k <= acc + h) { s_bin = t * CHUNKB + b; s_m1 = acc; }
                    acc += h;
                }
            }
        }
        __syncthreads();

        int binb = s_bin, m1 = s_m1;
        // ---- phase 2: classify into sw; threshold bin -> candidates
        for (int i = t; i < n; i += RPT) {
            unsigned key = cand_key[i];
            int bin = (int)(key >> 21);
            if (bin > binb) {
                sw[i] = key_score(key) * invk;
            } else if (bin < binb) {
                sw[i] = 0.0f;
            } else {
                int c = atomicAdd(&s_ncand, 1);
                cand_idx[c] = i;
            }
        }
        __syncthreads();
        int nc = s_ncand;
        unsigned mykey[2];
        int myidx[2];
        int mycnt = 0;
        for (int c = t; c < nc; c += RPT) {
            myidx[mycnt] = cand_idx[c];
            mykey[mycnt] = cand_key[cand_idx[c]];
            ++mycnt;
        }
        __syncthreads();
        for (int c = t, m = 0; c < nc; c += RPT, ++m) cand_key[c] = mykey[m];
        __syncthreads();

        int r = k - m1;
        for (int c = t, m = 0; c < nc; c += RPT, ++m) {
            unsigned ki = mykey[m];
            int ii = myidx[m];
            int cnt = 0;
            for (int j = 0; j < nc; ++j) {
                unsigned kj = cand_key[j];
                cnt += (kj > ki) || (kj == ki && cand_idx[j] < ii);
            }
            sw[ii] = (cnt < r) ? key_score(ki) * invk : 0.0f;
        }
        __syncthreads();

        // ---- phase 3: pool. Dual-row stream per thread for 2x MLP.
        int q  = t & 15;        // col quad
        int rg = t >> 4;        // row group (32)
        const float4* xv = (const float4*)x;
        float4 acc0 = make_float4(0.f, 0.f, 0.f, 0.f);
        float4 acc1 = make_float4(0.f, 0.f, 0.f, 0.f);
        int i = rg;
#pragma unroll 4
        for (; i + 32 < n; i += 64) {
            float w0 = sw[i];
            float w1 = sw[i + 32];
            float4 v0 = xv[(size_t)(start + i) * 16 + q];
            float4 v1 = xv[(size_t)(start + i + 32) * 16 + q];
            acc0.x += w0 * v0.x; acc0.y += w0 * v0.y;
            acc0.z += w0 * v0.z; acc0.w += w0 * v0.w;
            acc1.x += w1 * v1.x; acc1.y += w1 * v1.y;
            acc1.z += w1 * v1.z; acc1.w += w1 * v1.w;
        }
        if (i < n) {
            float w = sw[i];
            float4 v = xv[(size_t)(start + i) * 16 + q];
            acc0.x += w * v.x; acc0.y += w * v.y;
            acc0.z += w * v.z; acc0.w += w * v.w;
        }
        acc0.x += acc1.x; acc0.y += acc1.y;
        acc0.z += acc1.z; acc0.w += acc1.w;
        ps[rg][q * 4 + 0] = acc0.x;
        ps[rg][q * 4 + 1] = acc0.y;
        ps[rg][q * 4 + 2] = acc0.z;
        ps[rg][q * 4 + 3] = acc0.w;
        __syncthreads();
        if (t < 64) {
            float v = 0.0f;
#pragma unroll
            for (int j = 0; j < 32; ++j) v += ps[j][t];
            out[g * 64 + t] = v;
        }
    } else {
        // ---- improbable fallback: global O(n^2) + pool from d_w
        for (int i = t; i < n; i += RPT)
            d_score[start + i] = tanhf(d_s[start + i] + bias + d_r[start + i]);
        __syncthreads();
        for (int i = t; i < n; i += RPT) {
            float si = d_score[start + i];
            int cnt = 0;
            for (int j = 0; j < i; ++j)     cnt += (d_score[start + j] >= si);
            for (int j = i + 1; j < n; ++j) cnt += (d_score[start + j] >  si);
            d_w[start + i] = (cnt < k) ? si * invk : 0.0f;
        }
        __syncthreads();
        int q  = t & 15;
        int rg = t >> 4;
        const float4* xv = (const float4*)x;
        float4 acc = make_float4(0.f, 0.f, 0.f, 0.f);
        for (int i = rg; i < n; i += 32) {
            float w  = d_w[start + i];
            float4 v = xv[(size_t)(start + i) * 16 + q];
            acc.x += w * v.x; acc.y += w * v.y;
            acc.z += w * v.z; acc.w += w * v.w;
        }
        ps[rg][q * 4 + 0] = acc.x;
        ps[rg][q * 4 + 1] = acc.y;
        ps[rg][q * 4 + 2] = acc.z;
        ps[rg][q * 4 + 3] = acc.w;
        __syncthreads();
        if (t < 64) {
            float v = 0.0f;
#pragma unroll
            for (int j = 0; j < 32; ++j) v += ps[j][t];
            out[g * 64 + t] = v;
        }
    }
}

// ---------------------------------------------------------------------------
extern "C" void kernel_launch(void* const* d_in, const int* in_sizes, int n_in,
                              void* d_out, int out_size) {
    const float* x      = (const float*)d_in[0];
    const int*   ei     = (const int*)d_in[1];
    const int*   batch  = (const int*)d_in[2];
    const float* w_rel  = (const float*)d_in[3];
    const float* b_rel  = (const float*)d_in[4];
    const float* w_root = (const float*)d_in[5];
    float*       out    = (float*)d_out;

    int N = in_sizes[2];
    int E = in_sizes[1] / 2;

    {
        long long threads = (long long)N * 8;
        int blocks = (int)((threads + 255) / 256);
        k_node_dots<<<blocks, 256>>>(x, w_rel, w_root, batch, out, N);
    }
    {
        int E8 = E >> 3;
        int work = E8 > 8 ? E8 : 8;     // cover tail even when E8 == 0
        k_edge_scatter<<<(work + 255) / 256, 256>>>(ei, E);
    }
    k_rank_pool<<<NGRAPH, RPT>>>(x, b_rel, out);
}

// round 16
// speedup vs baseline: 1.2626x; 1.0554x over previous
#include <cuda_runtime.h>
#include <math.h>

#define MAX_N    131072
#define NGRAPH   256
#define MAXSEG   1024
#define NBINS    2048
#define RPT      512     // rank_pool threads
#define CHUNKB   4       // bins per thread (2048/512)

// Scratch (static __device__ arrays — no allocation allowed)
__device__ float d_p[MAX_N];        // x[i] . w_rel
__device__ float d_r[MAX_N];        // x[i].w_root  +  sum_{edges} p[src]  (merged accumulator)
__device__ float d_score[MAX_N];    // fallback scratch only
__device__ float d_w[MAX_N];        // fallback scratch only
__device__ int   d_starts[NGRAPH + 1];

__device__ __forceinline__ unsigned score_key(float s) {
    unsigned u = __float_as_uint(s);
    return (u & 0x80000000u) ? ~u : (u | 0x80000000u);   // monotone
}
__device__ __forceinline__ float key_score(unsigned k) {
    return (k & 0x80000000u) ? __uint_as_float(k & 0x7fffffffu)
                             : __uint_as_float(~k);
}
__device__ __forceinline__ float dot4(float4 a, float4 b) {
    return a.x * b.x + a.y * b.y + a.z * b.z + a.w * b.w;
}

// ---------------------------------------------------------------------------
// K0: per-node dots (8 threads/node, 2x float4). d_r holds x.w_root and will
// be atomically accumulated by the edge scatter. Segment-start detection.
// ---------------------------------------------------------------------------
__global__ void k_node_dots(const float* __restrict__ x,
                            const float* __restrict__ w_rel,
                            const float* __restrict__ w_root,
                            const int* __restrict__ batch,
                            int N) {
    int gid = blockIdx.x * blockDim.x + threadIdx.x;
    int node = gid >> 3;
    if (node >= N) return;
    int sub = gid & 7;
    const float4* xr = (const float4*)(x + (size_t)node * 64);
    float4 v0 = xr[sub];
    float4 v1 = xr[sub + 8];
    const float4* wrv = (const float4*)w_rel;
    const float4* wtv = (const float4*)w_root;
    float a = dot4(v0, wrv[sub]) + dot4(v1, wrv[sub + 8]);
    float b = dot4(v0, wtv[sub]) + dot4(v1, wtv[sub + 8]);
#pragma unroll
    for (int o = 4; o; o >>= 1) {
        a += __shfl_xor_sync(0xffffffffu, a, o);
        b += __shfl_xor_sync(0xffffffffu, b, o);
    }
    if (sub == 0) {
        d_p[node] = a;
        d_r[node] = b;
        int bi = batch[node];
        if (node == 0) {
            for (int g = 0; g <= bi; ++g) d_starts[g] = 0;
        } else {
            int bp = batch[node - 1];
            for (int g = bp + 1; g <= bi; ++g) d_starts[g] = node;
        }
        if (node == N - 1) {
            for (int g = bi + 1; g <= NGRAPH; ++g) d_starts[g] = N;
        }
    }
}

// ---------------------------------------------------------------------------
// K1: edge scatter  r[dst] += p[src].  8 edges/thread; streaming ei loads.
// ---------------------------------------------------------------------------
__global__ void k_edge_scatter(const int* __restrict__ ei, int E) {
    int t = blockIdx.x * blockDim.x + threadIdx.x;
    int E8 = E >> 3;
    if (t < E8) {
        const int4* sv = (const int4*)ei;
        const int4* dv = (const int4*)(ei + E);
        int4 sa = __ldcs(&sv[2 * t]);
        int4 sb = __ldcs(&sv[2 * t + 1]);
        int4 da = __ldcs(&dv[2 * t]);
        int4 db = __ldcs(&dv[2 * t + 1]);
        float p0 = d_p[sa.x], p1 = d_p[sa.y], p2 = d_p[sa.z], p3 = d_p[sa.w];
        float p4 = d_p[sb.x], p5 = d_p[sb.y], p6 = d_p[sb.z], p7 = d_p[sb.w];
        atomicAdd(&d_r[da.x], p0);
        atomicAdd(&d_r[da.y], p1);
        atomicAdd(&d_r[da.z], p2);
        atomicAdd(&d_r[da.w], p3);
        atomicAdd(&d_r[db.x], p4);
        atomicAdd(&d_r[db.y], p5);
        atomicAdd(&d_r[db.z], p6);
        atomicAdd(&d_r[db.w], p7);
    }
    int base = E8 << 3;
    int rem = E - base;
    if (t < rem) {
        atomicAdd(&d_r[__ldcs(&ei[E + base + t])], d_p[__ldcs(&ei[base + t])]);
    }
}

// ---------------------------------------------------------------------------
// K2: fused per-graph score + histogram top-k select + weighted mean pool.
// 512 threads, one block per graph, starts precomputed. Exact lexsort ties.
// ---------------------------------------------------------------------------
__global__ void __launch_bounds__(RPT)
k_rank_pool(const float* __restrict__ x,
            const float* __restrict__ b_rel,
            float* __restrict__ out) {
    __shared__ unsigned hist[NBINS];
    __shared__ float    sw[MAXSEG];
    __shared__ unsigned chsum[RPT];
    __shared__ unsigned suf[RPT];
    __shared__ int s_bin, s_m1, s_ncand;
    __shared__ int      cand_idx[MAXSEG];
    __shared__ unsigned cand_key[MAXSEG];
    __shared__ float ps[32][64];

    int g = blockIdx.x;
    int t = threadIdx.x;

    if (t == 0) { s_bin = -1; s_m1 = 0; s_ncand = 0; }
#pragma unroll
    for (int b = 0; b < CHUNKB; ++b) hist[t * CHUNKB + b] = 0;

    int start = d_starts[g];
    int end   = d_starts[g + 1];
    int n = end - start;
    int k = (n + 1) >> 1;
    float invk = 1.0f / fmaxf((float)k, 1.0f);
    float bias = b_rel[0];
    __syncthreads();

    if (n <= MAXSEG) {
        // ---- phase 1: keys + histogram (keys by position in cand_key)
        for (int i = t; i < n; i += RPT) {
            float sc = tanhf(d_r[start + i] + bias);
            unsigned key = score_key(sc);
            cand_key[i] = key;
            atomicAdd(&hist[key >> 21], 1u);
        }
        __syncthreads();

        unsigned cs = 0;
#pragma unroll
        for (int b = 0; b < CHUNKB; ++b) cs += hist[t * CHUNKB + b];
        chsum[t] = cs;
        __syncthreads();

        // single-warp suffix scan over 512 chunk sums (16 per lane)
        if (t < 32) {
            unsigned v[16];
            unsigned tot = 0;
#pragma unroll
            for (int j = 15; j >= 0; --j) {
                tot += chsum[t * 16 + j];
                v[j] = tot;
            }
            unsigned run = tot;
#pragma unroll
            for (int off = 1; off < 32; off <<= 1) {
                unsigned q = __shfl_down_sync(0xffffffffu, run, off);
                if (t + off < 32) run += q;
            }
            unsigned tail = run - tot;
#pragma unroll
            for (int j = 0; j < 16; ++j) suf[t * 16 + j] = v[j] + tail;
        }
        __syncthreads();

        {
            unsigned above = suf[t] - chsum[t];
            if ((int)above < k && k <= (int)suf[t]) {
                int acc = (int)above;
                for (int b = CHUNKB - 1; b >= 0; --b) {
                    int h = (int)hist[t * CHUNKB + b];
                    if (acc < k && k <= acc + h) { s_bin = t * CHUNKB + b; s_m1 = acc; }
                    acc += h;
                }
            }
        }
        __syncthreads();

        int binb = s_bin, m1 = s_m1;
        // ---- phase 2: classify into sw; threshold bin -> candidates
        for (int i = t; i < n; i += RPT) {
            unsigned key = cand_key[i];
            int bin = (int)(key >> 21);
            if (bin > binb) {
                sw[i] = key_score(key) * invk;
            } else if (bin < binb) {
                sw[i] = 0.0f;
            } else {
                int c = atomicAdd(&s_ncand, 1);
                cand_idx[c] = i;
            }
        }
        __syncthreads();
        int nc = s_ncand;
        unsigned mykey[2];
        int myidx[2];
        int mycnt = 0;
        for (int c = t; c < nc; c += RPT) {
            myidx[mycnt] = cand_idx[c];
            mykey[mycnt] = cand_key[cand_idx[c]];
            ++mycnt;
        }
        __syncthreads();
        for (int c = t, m = 0; c < nc; c += RPT, ++m) cand_key[c] = mykey[m];
        __syncthreads();

        int r = k - m1;
        for (int c = t, m = 0; c < nc; c += RPT, ++m) {
            unsigned ki = mykey[m];
            int ii = myidx[m];
            int cnt = 0;
            for (int j = 0; j < nc; ++j) {
                unsigned kj = cand_key[j];
                cnt += (kj > ki) || (kj == ki && cand_idx[j] < ii);
            }
            sw[ii] = (cnt < r) ? key_score(ki) * invk : 0.0f;
        }
        __syncthreads();

        // ---- phase 3: pool. Dual-row stream per thread for 2x MLP.
        int q  = t & 15;        // col quad
        int rg = t >> 4;        // row group (32)
        const float4* xv = (const float4*)x;
        float4 acc0 = make_float4(0.f, 0.f, 0.f, 0.f);
        float4 acc1 = make_float4(0.f, 0.f, 0.f, 0.f);
        int i = rg;
#pragma unroll 4
        for (; i + 32 < n; i += 64) {
            float w0 = sw[i];
            float w1 = sw[i + 32];
            float4 v0 = xv[(size_t)(start + i) * 16 + q];
            float4 v1 = xv[(size_t)(start + i + 32) * 16 + q];
            acc0.x += w0 * v0.x; acc0.y += w0 * v0.y;
            acc0.z += w0 * v0.z; acc0.w += w0 * v0.w;
            acc1.x += w1 * v1.x; acc1.y += w1 * v1.y;
            acc1.z += w1 * v1.z; acc1.w += w1 * v1.w;
        }
        if (i < n) {
            float w = sw[i];
            float4 v = xv[(size_t)(start + i) * 16 + q];
            acc0.x += w * v.x; acc0.y += w * v.y;
            acc0.z += w * v.z; acc0.w += w * v.w;
        }
        acc0.x += acc1.x; acc0.y += acc1.y;
        acc0.z += acc1.z; acc0.w += acc1.w;
        ps[rg][q * 4 + 0] = acc0.x;
        ps[rg][q * 4 + 1] = acc0.y;
        ps[rg][q * 4 + 2] = acc0.z;
        ps[rg][q * 4 + 3] = acc0.w;
        __syncthreads();
        if (t < 64) {
            float v = 0.0f;
#pragma unroll
            for (int j = 0; j < 32; ++j) v += ps[j][t];
            out[g * 64 + t] = v;
        }
    } else {
        // ---- improbable fallback: global O(n^2) + pool from d_w
        for (int i = t; i < n; i += RPT)
            d_score[start + i] = tanhf(d_r[start + i] + bias);
        __syncthreads();
        for (int i = t; i < n; i += RPT) {
            float si = d_score[start + i];
            int cnt = 0;
            for (int j = 0; j < i; ++j)     cnt += (d_score[start + j] >= si);
            for (int j = i + 1; j < n; ++j) cnt += (d_score[start + j] >  si);
            d_w[start + i] = (cnt < k) ? si * invk : 0.0f;
        }
        __syncthreads();
        int q  = t & 15;
        int rg = t >> 4;
        const float4* xv = (const float4*)x;
        float4 acc = make_float4(0.f, 0.f, 0.f, 0.f);
        for (int i = rg; i < n; i += 32) {
            float w  = d_w[start + i];
            float4 v = xv[(size_t)(start + i) * 16 + q];
            acc.x += w * v.x; acc.y += w * v.y;
            acc.z += w * v.z; acc.w += w * v.w;
        }
        ps[rg][q * 4 + 0] = acc.x;
        ps[rg][q * 4 + 1] = acc.y;
        ps[rg][q * 4 + 2] = acc.z;
        ps[rg][q * 4 + 3] = acc.w;
        __syncthreads();
        if (t < 64) {
            float v = 0.0f;
#pragma unroll
            for (int j = 0; j < 32; ++j) v += ps[j][t];
            out[g * 64 + t] = v;
        }
    }
}

// ---------------------------------------------------------------------------
extern "C" void kernel_launch(void* const* d_in, const int* in_sizes, int n_in,
                              void* d_out, int out_size) {
    const float* x      = (const float*)d_in[0];
    const int*   ei     = (const int*)d_in[1];
    const int*   batch  = (const int*)d_in[2];
    const float* w_rel  = (const float*)d_in[3];
    const float* b_rel  = (const float*)d_in[4];
    const float* w_root = (const float*)d_in[5];
    float*       out    = (float*)d_out;

    int N = in_sizes[2];
    int E = in_sizes[1] / 2;

    {
        long long threads = (long long)N * 8;
        int blocks = (int)((threads + 255) / 256);
        k_node_dots<<<blocks, 256>>>(x, w_rel, w_root, batch, N);
    }
    {
        int E8 = E >> 3;
        int work = E8 > 8 ? E8 : 8;     // cover tail even when E8 == 0
        k_edge_scatter<<<(work + 255) / 256, 256>>>(ei, E);
    }
    k_rank_pool<<<NGRAPH, RPT>>>(x, b_rel, out);
}